// round 10
// baseline (speedup 1.0000x reference)
#include <cuda_runtime.h>
#include <cuda_bf16.h>

#define NPTS   65536
#define CHN    256
#define BATCH  16
#define LOUT   8192
#define LOG2L  13

// ----------------------------------------------------------- single kernel -
// blocks [0, PT_BLOCKS)             : points gather (8 blocks per batch b)
// blocks [PT_BLOCKS, PT_BLOCKS+2048): feature gather-transpose
//                                     (128 blocks per b; thread owns 4 j-quads)
//
// Prolog: warps 0/1 run a 32-ary cooperative lower_bound over the sorted
// batch array (4 dependent probe rounds) for keys b and b+1 -> (off, cnt).
// No separate boundary kernel, no PDL, one launch.
#define PT_BLOCKS 128

__global__ __launch_bounds__(256)
void gather_kernel(const float* __restrict__ px,
                   const float4* __restrict__ feat4,
                   const int* __restrict__ batch,
                   float* __restrict__ out_point,
                   float* __restrict__ out_feat) {
    __shared__ int s_bound[2];
    int bid = blockIdx.x;
    int tid = threadIdx.x;
    int w = tid >> 5, L = tid & 31;

    // Block-uniform batch id.
    int b = (bid < PT_BLOCKS) ? (bid >> 3) : ((bid - PT_BLOCKS) >> 7);

    // ---- warp-cooperative lower_bound: boundary in (lo, lo+len], len 32-ary.
    if (w < 2) {
        int key = b + w;
        int lo = -1;
        int s = 2048;                     // 65536 -> 2048 -> 64 -> 2
        #pragma unroll
        for (int lev = 0; lev < 3; lev++) {
            int pos = lo + (L + 1) * s;
            int val = (pos < NPTS) ? __ldg(&batch[pos]) : 0x7fffffff;
            unsigned m = __ballot_sync(0xffffffffu, val < key);
            lo += __popc(m) * s;
            s >>= 5;
        }
        // len == 2: probe lo+1, lo+2 with lanes 0,1.
        bool pred = false;
        if (L < 2) {
            int pos = lo + 1 + L;
            pred = (pos < NPTS) && (__ldg(&batch[pos]) < key);
        }
        unsigned m = __ballot_sync(0xffffffffu, pred);
        if (L == 0) s_bound[w] = lo + 1 + __popc(m);
    }
    __syncthreads();
    int off = s_bound[0];
    int cnt = s_bound[1] - off;

    if (bid < PT_BLOCKS) {
        // ---- points: thread = 4 consecutive j; float4 writes.
        int idx = bid * 256 + tid;            // 0..32767
        int j = (idx & 2047) * 4;
        float4 ox, oy, oz;
        #pragma unroll
        for (int t = 0; t < 4; t++) {
            int src = off + (int)(((unsigned)((j + t) * cnt)) >> LOG2L);
            const float* p = px + 3 * src;
            ((float*)&ox)[t] = p[0];
            ((float*)&oy)[t] = p[1];
            ((float*)&oz)[t] = p[2];
        }
        size_t base = (size_t)b * 3 * LOUT + j;
        __stcs((float4*)(out_point + base),            ox);
        __stcs((float4*)(out_point + base + LOUT),     oy);
        __stcs((float4*)(out_point + base + 2 * LOUT), oz);
        return;
    }

    // ---- features: block = (b, c4, half); thread owns 4 j-quads.
    int r    = (bid - PT_BLOCKS) & 127;
    int c4   = r >> 1;                        // 0..63
    int half = r & 1;
    int base_jq = half * 1024 + w * 128 + L;  // + q*32, q = 0..3

    const float4* fb = feat4 + c4;
    float* obase = out_feat + ((size_t)b * CHN + 4 * c4) * LOUT;

    #pragma unroll
    for (int q = 0; q < 4; q++) {
        int j0 = (base_jq + q * 32) * 4;

        // Monotone source rows; load endpoints, select/rare-load interiors.
        int r0 = off + (int)(((unsigned)((j0 + 0) * cnt)) >> LOG2L);
        int r1 = off + (int)(((unsigned)((j0 + 1) * cnt)) >> LOG2L);
        int r2 = off + (int)(((unsigned)((j0 + 2) * cnt)) >> LOG2L);
        int r3 = off + (int)(((unsigned)((j0 + 3) * cnt)) >> LOG2L);

        float4 A = __ldg(fb + (size_t)r0 * (CHN / 4));
        float4 D = __ldg(fb + (size_t)r3 * (CHN / 4));
        float4 v1 = (r1 == r0) ? A : D;
        if (r1 > r0 && r1 < r3) v1 = __ldg(fb + (size_t)r1 * (CHN / 4));
        float4 v2 = (r2 == r3) ? D : A;
        if (r2 > r0 && r2 < r3) v2 = __ldg(fb + (size_t)r2 * (CHN / 4));

        // 4x4 register transpose + warp-contiguous float4 stores.
        float* ob = obase + j0;
        float4 o;
        o.x = A.x;  o.y = v1.x; o.z = v2.x; o.w = D.x;
        __stcs((float4*)(ob + 0 * LOUT), o);
        o.x = A.y;  o.y = v1.y; o.z = v2.y; o.w = D.y;
        __stcs((float4*)(ob + 1 * LOUT), o);
        o.x = A.z;  o.y = v1.z; o.z = v2.z; o.w = D.z;
        __stcs((float4*)(ob + 2 * LOUT), o);
        o.x = A.w;  o.y = v1.w; o.z = v2.w; o.w = D.w;
        __stcs((float4*)(ob + 3 * LOUT), o);
    }
}

// ------------------------------------------------------------- launch ------
extern "C" void kernel_launch(void* const* d_in, const int* in_sizes, int n_in,
                              void* d_out, int out_size) {
    const float* points_x = (const float*)d_in[0];   // [N,3]
    const float* feat     = (const float*)d_in[1];   // [N,C]
    const int*   batch    = (const int*)d_in[2];     // [N]

    float* out_point = (float*)d_out;                              // [B,3,L]
    float* out_feat  = (float*)d_out + (size_t)BATCH * 3 * LOUT;   // [B,C,L]

    gather_kernel<<<PT_BLOCKS + 2048, 256>>>(points_x, (const float4*)feat,
                                             batch, out_point, out_feat);
}